// round 5
// baseline (speedup 1.0000x reference)
#include <cuda_runtime.h>

// ---------------------------------------------------------------------------
// SINDy autoencoder forward. Output: [z|dz|dzb|xb|dxb] = 32816 f32.
// R5: middle chain (enc1 + small + dec1) fused into one persistent 148-block
//     kernel with grid barriers; idle blocks prefetch upcoming weights to L2.
// ---------------------------------------------------------------------------

#define W0_OUT 4096
#define W0_IN  16384
#define W1_OUT 1024
#define LATENT 16
#define SINDY_DIM 984
#define NBLK 148
#define FTHREADS 512

__device__ float g_pre1[W0_OUT], g_u1[W0_OUT];
__device__ float g_pre2p[2 * W1_OUT], g_u2p[2 * W1_OUT];
__device__ float g_g1[1024],  g_p1[1024];
__device__ float g_q2[4096],  g_v2[4096];

// grid barrier state (sense-reversing; self-resetting across graph replays)
__device__ unsigned g_bar_cnt[2];
__device__ unsigned g_bar_sense[2];

__device__ __forceinline__ float sigf(float x) { return 1.0f / (1.0f + __expf(-x)); }
__device__ __forceinline__ float4 ldcs4(const float* p) { return __ldcs((const float4*)p); }

__device__ __forceinline__ void pdl_trigger() {
    asm volatile("griddepcontrol.launch_dependents;" ::: "memory");
}
__device__ __forceinline__ void pdl_wait() {
    asm volatile("griddepcontrol.wait;" ::: "memory");
}
__device__ __forceinline__ void l2_prefetch(const void* p) {
    asm volatile("prefetch.global.L2 [%0];" :: "l"(p));
}
template<int THREADS>
__device__ __forceinline__ void prefetch_tile(const float* base, size_t bytes) {
    const char* p = (const char*)base;
    for (size_t off = (size_t)threadIdx.x * 128; off < bytes; off += (size_t)THREADS * 128)
        l2_prefetch(p + off);
}

__device__ __forceinline__ void grid_barrier(int id) {
    __syncthreads();
    if (threadIdx.x == 0) {
        __threadfence();
        unsigned s = ((volatile unsigned*)g_bar_sense)[id];
        if (atomicAdd(&g_bar_cnt[id], 1u) == NBLK - 1) {
            g_bar_cnt[id] = 0;
            __threadfence();
            atomicExch(&g_bar_sense[id], s ^ 1u);
        } else {
            while (((volatile unsigned*)g_bar_sense)[id] == s) { }
        }
        __threadfence();
    }
    __syncthreads();
}

// ---------------------------------------------------------------------------
// Dual matvec (ROWS=4) for the two big kernels — unchanged from R4.
// ---------------------------------------------------------------------------
template<int KSTRIDE, int KCHUNK, int ROWS, int THREADS, bool SIG>
__device__ __forceinline__ void dual_body(
    const float* __restrict__ W,
    const float* __restrict__ av,
    const float* __restrict__ bv,
    const float* __restrict__ bias,
    float* __restrict__ outA,
    float* __restrict__ outB,
    int row0)
{
    constexpr int NW = THREADS / 32;
    constexpr int ITERS = KCHUNK / (THREADS * 4);
    const int tid = threadIdx.x;

    float accA[ROWS], accB[ROWS];
#pragma unroll
    for (int r = 0; r < ROWS; r++) { accA[r] = 0.0f; accB[r] = 0.0f; }

#pragma unroll 2
    for (int it = 0; it < ITERS; it++) {
        const int k = (it * THREADS + tid) * 4;
        float4 w4[ROWS];
#pragma unroll
        for (int r = 0; r < ROWS; r++)
            w4[r] = ldcs4(W + (size_t)r * KSTRIDE + k);
        float4 a4 = *(const float4*)(av + k);
        float4 b4 = *(const float4*)(bv + k);
        if (SIG) {
            float s;
            s = sigf(a4.x); b4.x *= s * (1.0f - s); a4.x = s;
            s = sigf(a4.y); b4.y *= s * (1.0f - s); a4.y = s;
            s = sigf(a4.z); b4.z *= s * (1.0f - s); a4.z = s;
            s = sigf(a4.w); b4.w *= s * (1.0f - s); a4.w = s;
        }
#pragma unroll
        for (int r = 0; r < ROWS; r++) {
            accA[r] = fmaf(w4[r].x, a4.x, accA[r]);
            accA[r] = fmaf(w4[r].y, a4.y, accA[r]);
            accA[r] = fmaf(w4[r].z, a4.z, accA[r]);
            accA[r] = fmaf(w4[r].w, a4.w, accA[r]);
            accB[r] = fmaf(w4[r].x, b4.x, accB[r]);
            accB[r] = fmaf(w4[r].y, b4.y, accB[r]);
            accB[r] = fmaf(w4[r].z, b4.z, accB[r]);
            accB[r] = fmaf(w4[r].w, b4.w, accB[r]);
        }
    }

    __shared__ float sA[NW][ROWS], sB[NW][ROWS];
    const int lane = tid & 31, warp = tid >> 5;
#pragma unroll
    for (int r = 0; r < ROWS; r++) {
        float vA = accA[r], vB = accB[r];
#pragma unroll
        for (int o = 16; o; o >>= 1) {
            vA += __shfl_xor_sync(0xffffffffu, vA, o);
            vB += __shfl_xor_sync(0xffffffffu, vB, o);
        }
        if (lane == 0) { sA[warp][r] = vA; sB[warp][r] = vB; }
    }
    __syncthreads();
    if (tid < ROWS) {
        float vA = 0.0f, vB = 0.0f;
#pragma unroll
        for (int w = 0; w < NW; w++) { vA += sA[w][tid]; vB += sB[w][tid]; }
        if (bias) vA += bias[row0 + tid];
        outA[row0 + tid] = vA;
        outB[row0 + tid] = vB;
    }
}

// enc L0 (256 MB): pre1 = W0 @ x + b0 ; u1 = W0 @ dx
__global__ void __launch_bounds__(256) k_enc0(
    const float* __restrict__ W, const float* __restrict__ x,
    const float* __restrict__ dx, const float* __restrict__ b)
{
    pdl_trigger();
    const int row0 = blockIdx.x * 4;
    dual_body<W0_IN, W0_IN, 4, 256, false>(
        W + (size_t)row0 * W0_IN, x, dx, b, g_pre1, g_u1, row0);
}

// dec L2 (256 MB): xb, dxb -> out
__global__ void __launch_bounds__(256) k_dec2(
    const float* __restrict__ W, const float* __restrict__ b,
    float* __restrict__ out)
{
    const int row0 = blockIdx.x * 4;
    const float* Wt = W + (size_t)row0 * 4096;
    prefetch_tile<256>(Wt, 4 * 4096 * 4);
    pdl_wait();
    dual_body<4096, 4096, 4, 256, true>(
        Wt, g_q2, g_v2, b, out + 48, out + 48 + 16384, row0);
}

// ---------------------------------------------------------------------------
// Fused middle kernel: 148 blocks x 512 threads, 206KB dyn smem each.
//   Phase A: enc L1 (split-K x2, warp-per-(row,split)); idle blocks prefetch.
//   Phase B: block 0 = small chain; others prefetch wd_w2 head.
//   Phase C: dec L1, warp-per-row, all blocks.
// smem layout (floats) for phase B (block 0):
// ---------------------------------------------------------------------------
#define SM_WE2   0
#define SM_EW    16384
#define SM_WD0   32128
#define SM_H2    48512
#define SM_T2    49536
#define SM_THETA 50560
#define SM_FLOATS 51544
#define SM_BYTES (SM_FLOATS * 4)

__global__ void __launch_bounds__(FTHREADS, 1) k_mid(
    const float* __restrict__ we_w1, const float* __restrict__ we_b1,
    const float* __restrict__ we_w2, const float* __restrict__ we_b2,
    const float* __restrict__ E_w,   const float* __restrict__ E_b,
    const float* __restrict__ wd_w0, const float* __restrict__ wd_b0,
    const float* __restrict__ wd_w1, const float* __restrict__ wd_b1,
    const float* __restrict__ wd_w2,
    float* __restrict__ out)
{
    extern __shared__ float sm[];
    __shared__ float z[LATENT], dz[LATENT], dzb[LATENT];

    const int tid  = threadIdx.x;
    const int lane = tid & 31, wid = tid >> 5;        // 16 warps
    const int bx   = blockIdx.x;

    pdl_trigger();

    // ======== Phase A: enc L1  (pre2 = W1 @ sig(pre1) + b1 ; u2 = W1 @ t1) ====
    if (bx < 128) {
        // idle-free: all 128 blocks compute. First (before data dep): nothing.
        pdl_wait();
        // stage h1/t1 for this block (32 KB smem)
        for (int i = tid; i < W0_OUT; i += FTHREADS) {
            float s = sigf(g_pre1[i]);
            sm[i] = s;                       // h1
            sm[W0_OUT + i] = s * (1.0f - s) * g_u1[i];   // t1
        }
        __syncthreads();

        const int gw    = bx * 16 + wid;     // 0..2047
        const int row   = gw & 1023;
        const int split = gw >> 10;          // 0 or 1
        const int koff  = split * 2048;

        float aacc = 0.0f, bacc = 0.0f;
        const float* wr = we_w1 + (size_t)row * W0_OUT + koff;
#pragma unroll 4
        for (int it = 0; it < 16; it++) {
            const int k = (it * 32 + lane) * 4;
            float4 w4 = ldcs4(wr + k);
            float4 a4 = *(const float4*)(sm + koff + k);
            float4 b4 = *(const float4*)(sm + W0_OUT + koff + k);
            aacc = fmaf(w4.x, a4.x, aacc); aacc = fmaf(w4.y, a4.y, aacc);
            aacc = fmaf(w4.z, a4.z, aacc); aacc = fmaf(w4.w, a4.w, aacc);
            bacc = fmaf(w4.x, b4.x, bacc); bacc = fmaf(w4.y, b4.y, bacc);
            bacc = fmaf(w4.z, b4.z, bacc); bacc = fmaf(w4.w, b4.w, bacc);
        }
#pragma unroll
        for (int o = 16; o; o >>= 1) {
            aacc += __shfl_xor_sync(0xffffffffu, aacc, o);
            bacc += __shfl_xor_sync(0xffffffffu, bacc, o);
        }
        if (lane == 0) {
            if (split == 0) aacc += we_b1[row];
            g_pre2p[split * W1_OUT + row] = aacc;
            g_u2p[split * W1_OUT + row]   = bacc;
        }
    } else {
        // blocks 128..147: prefetch next-phase weights into L2
        if (bx == 128) {
            prefetch_tile<FTHREADS>(we_w2, 16384 * 4);
            prefetch_tile<FTHREADS>(E_w,   15744 * 4);
            prefetch_tile<FTHREADS>(wd_w0, 16384 * 4);
        } else {
            // 19 blocks cover wd_w1 (16 MB)
            const int pb = bx - 129;  // 0..18
            const size_t total = (size_t)4096 * 1024 * 4;
            const size_t chunk = (total + 18) / 19;
            size_t beg = pb * chunk, end = beg + chunk;
            if (end > total) end = total;
            const char* p = (const char*)wd_w1;
            for (size_t off = beg + (size_t)tid * 128; off < end; off += (size_t)FTHREADS * 128)
                l2_prefetch(p + off);
        }
        pdl_wait();
    }

    grid_barrier(0);

    // ======== Phase B: block 0 small chain; others prefetch wd_w2 head ========
    if (bx == 0) {
        for (int i = tid; i < 4096; i += FTHREADS)
            *(float4*)(sm + SM_WE2 + i * 4) = ldcs4(we_w2 + i * 4);
        for (int i = tid; i < 3936; i += FTHREADS)
            *(float4*)(sm + SM_EW + i * 4) = ldcs4(E_w + i * 4);
        for (int i = tid; i < 4096; i += FTHREADS)
            *(float4*)(sm + SM_WD0 + i * 4) = ldcs4(wd_w0 + i * 4);
        for (int i = tid; i < W1_OUT; i += FTHREADS) {
            float pre = g_pre2p[i] + g_pre2p[W1_OUT + i];
            float u   = g_u2p[i]   + g_u2p[W1_OUT + i];
            float s = sigf(pre);
            sm[SM_H2 + i] = s;
            sm[SM_T2 + i] = s * (1.0f - s) * u;
        }
        __syncthreads();

        {   // z, dz (warp per row)
            float az = 0.0f, ad = 0.0f;
            const float* wr = sm + SM_WE2 + wid * W1_OUT;
            for (int c = lane; c < W1_OUT; c += 32) {
                float w = wr[c];
                az = fmaf(w, sm[SM_H2 + c], az);
                ad = fmaf(w, sm[SM_T2 + c], ad);
            }
#pragma unroll
            for (int o = 16; o; o >>= 1) {
                az += __shfl_xor_sync(0xffffffffu, az, o);
                ad += __shfl_xor_sync(0xffffffffu, ad, o);
            }
            if (lane == 0) { z[wid] = az + we_b2[wid]; dz[wid] = ad; }
        }
        __syncthreads();

        if (tid < LATENT) { out[tid] = z[tid]; out[LATENT + tid] = dz[tid]; }

        for (int idx = tid; idx < SINDY_DIM; idx += FTHREADS) {
            float v;
            if (idx < 16) v = 1.0f;
            else if (idx < 32) v = z[idx - 16];
            else if (idx < 168) {
                int q = idx - 32, i = 0;
                for (;;) { int m = 16 - i; if (q < m) break; q -= m; i++; }
                v = z[i] * z[i + q];
            } else {
                int t = idx - 168, i = 0;
                for (;;) { int m = 16 - i; int c = m * (m + 1) / 2; if (t < c) break; t -= c; i++; }
                int j = i;
                for (;;) { int m = 16 - j; if (t < m) break; t -= m; j++; }
                v = z[i] * z[j] * z[j + t];
            }
            sm[SM_THETA + idx] = v;
        }
        __syncthreads();

        {   // dzb
            float a = 0.0f;
            const float* er = sm + SM_EW + wid * SINDY_DIM;
            for (int c = lane; c < SINDY_DIM; c += 32)
                a = fmaf(er[c], sm[SM_THETA + c], a);
#pragma unroll
            for (int o = 16; o; o >>= 1)
                a += __shfl_xor_sync(0xffffffffu, a, o);
            if (lane == 0) dzb[wid] = a + E_b[wid];
        }
        __syncthreads();

        if (tid < LATENT) out[32 + tid] = dzb[tid];

        // dec L0 + activation -> g_g1/g_p1 (global, consumed in phase C)
        for (int row = tid; row < 1024; row += FTHREADS) {
            float a = wd_b0[row], bb = 0.0f;
            const float* wr = sm + SM_WD0 + row * LATENT;
#pragma unroll
            for (int c = 0; c < LATENT; c++) {
                float w = wr[c];
                a  = fmaf(w, z[c],   a);
                bb = fmaf(w, dzb[c], bb);
            }
            float s = sigf(a);
            g_g1[row] = s;
            g_p1[row] = s * (1.0f - s) * bb;
        }
    } else {
        // prefetch first 32 MB of wd_w2 (147 blocks share)
        const size_t total = (size_t)32 * 1024 * 1024;
        const size_t chunk = (total + 146) / 147;
        const int pb = bx - 1;
        size_t beg = pb * chunk, end = beg + chunk;
        if (end > total) end = total;
        const char* p = (const char*)wd_w2;
        for (size_t off = beg + (size_t)tid * 128; off < end; off += (size_t)FTHREADS * 128)
            l2_prefetch(p + off);
    }

    grid_barrier(1);

    // ======== Phase C: dec L1  (q2 = Wd1 @ g1 + bd1 ; v2 = Wd1 @ p1) =========
    // stage g1/p1 in smem (8 KB)
    for (int i = tid; i < 1024; i += FTHREADS) {
        sm[i]        = g_g1[i];
        sm[1024 + i] = g_p1[i];
    }
    __syncthreads();

    const int gw = bx * 16 + wid;   // 0..2367
#pragma unroll
    for (int rr = 0; rr < 2; rr++) {
        const int row = gw * 2 + rr;
        if (row < 4096) {
            float aacc = 0.0f, bacc = 0.0f;
            const float* wr = wd_w1 + (size_t)row * 1024;
#pragma unroll 4
            for (int it = 0; it < 8; it++) {
                const int k = (it * 32 + lane) * 4;
                float4 w4 = ldcs4(wr + k);
                float4 a4 = *(const float4*)(sm + k);
                float4 b4 = *(const float4*)(sm + 1024 + k);
                aacc = fmaf(w4.x, a4.x, aacc); aacc = fmaf(w4.y, a4.y, aacc);
                aacc = fmaf(w4.z, a4.z, aacc); aacc = fmaf(w4.w, a4.w, aacc);
                bacc = fmaf(w4.x, b4.x, bacc); bacc = fmaf(w4.y, b4.y, bacc);
                bacc = fmaf(w4.z, b4.z, bacc); bacc = fmaf(w4.w, b4.w, bacc);
            }
#pragma unroll
            for (int o = 16; o; o >>= 1) {
                aacc += __shfl_xor_sync(0xffffffffu, aacc, o);
                bacc += __shfl_xor_sync(0xffffffffu, bacc, o);
            }
            if (lane == 0) {
                g_q2[row] = aacc + wd_b1[row];
                g_v2[row] = bacc;
            }
        }
    }
}

// ---------------------------------------------------------------------------
extern "C" void kernel_launch(void* const* d_in, const int* in_sizes, int n_in,
                              void* d_out, int out_size)
{
    const float* x     = (const float*)d_in[0];
    const float* dx    = (const float*)d_in[1];
    const float* we_w0 = (const float*)d_in[3];
    const float* we_b0 = (const float*)d_in[4];
    const float* we_w1 = (const float*)d_in[5];
    const float* we_b1 = (const float*)d_in[6];
    const float* we_w2 = (const float*)d_in[7];
    const float* we_b2 = (const float*)d_in[8];
    const float* wd_w0 = (const float*)d_in[9];
    const float* wd_b0 = (const float*)d_in[10];
    const float* wd_w1 = (const float*)d_in[11];
    const float* wd_b1 = (const float*)d_in[12];
    const float* wd_w2 = (const float*)d_in[13];
    const float* wd_b2 = (const float*)d_in[14];
    const float* E_w   = (const float*)d_in[15];
    const float* E_b   = (const float*)d_in[16];
    float* out = (float*)d_out;

    cudaFuncSetAttribute(k_mid, cudaFuncAttributeMaxDynamicSharedMemorySize, SM_BYTES);

    cudaLaunchAttribute attr[1];
    attr[0].id = cudaLaunchAttributeProgrammaticStreamSerialization;
    attr[0].val.programmaticStreamSerializationAllowed = 1;

    cudaLaunchConfig_t cfg{};
    cfg.blockDim = dim3(256, 1, 1);
    cfg.stream = 0;
    cfg.attrs = attr;
    cfg.numAttrs = 1;

    // 1) enc L0 (256 MB)
    cfg.gridDim = dim3(W0_OUT / 4, 1, 1);
    cudaLaunchKernelEx(&cfg, k_enc0, we_w0, x, dx, we_b0);

    // 2) fused middle
    {
        cudaLaunchConfig_t cm = cfg;
        cm.gridDim = dim3(NBLK, 1, 1);
        cm.blockDim = dim3(FTHREADS, 1, 1);
        cm.dynamicSmemBytes = SM_BYTES;
        cudaLaunchKernelEx(&cm, k_mid,
                           we_w1, we_b1, we_w2, we_b2, E_w, E_b,
                           wd_w0, wd_b0, wd_w1, wd_b1, wd_w2, out);
    }

    // 3) dec L2 (256 MB)
    cfg.gridDim = dim3(16384 / 4, 1, 1);
    cudaLaunchKernelEx(&cfg, k_dec2, wd_w2, wd_b2, out);
}